// round 12
// baseline (speedup 1.0000x reference)
#include <cuda_runtime.h>
#include <math.h>

#define H      1024
#define BATCH  32
#define TSTEPS 512
#define INDIM  512
#define G4     (4*H)
#define NCTA3  128
#define NTHR3  256   // 8 warps; warp = 1 unit; 2 batch-groups of 16

// ---------------- scratch ----------------
__device__ float g_xz[(size_t)BATCH * TSTEPS * G4];   // 268 MB: x@W, [B*T, 4H]
__device__ float g_UT[(size_t)G4 * H];                // 16 MB: U transposed [4H][H]
__device__ float g_h2[2][2][16 * H];                  // [grp][parity][b_in*H + u]
__device__ unsigned g_cnt2[2][8 * 32];                // per-group monotonic counters

// ---------------- helpers ----------------
__device__ __forceinline__ void fma2(unsigned long long& d, unsigned long long a,
                                     unsigned long long b) {
    asm("fma.rn.f32x2 %0, %1, %2, %0;" : "+l"(d) : "l"(a), "l"(b));
}
__device__ __forceinline__ float hsum2(unsigned long long v) {
    float x, y;
    asm("mov.b64 {%0, %1}, %2;" : "=f"(x), "=f"(y) : "l"(v));
    return x + y;
}
__device__ __forceinline__ unsigned long long packdup(float a) {
    unsigned long long d;
    asm("mov.b64 %0, {%1, %1};" : "=l"(d) : "f"(a));
    return d;
}
__device__ __forceinline__ unsigned ld_cg_u32(const unsigned* p) {
    unsigned v;
    asm volatile("ld.global.cg.u32 %0, [%1];" : "=r"(v) : "l"(p) : "memory");
    return v;
}
__device__ __forceinline__ void cp_async16(unsigned smem_addr, const void* gptr) {
    asm volatile("cp.async.cg.shared.global [%0], [%1], 16;"
                 :: "r"(smem_addr), "l"(gptr) : "memory");
}
__device__ __forceinline__ void cp_commit() {
    asm volatile("cp.async.commit_group;" ::: "memory");
}
template <int N>
__device__ __forceinline__ void cp_wait() {
    asm volatile("cp.async.wait_group %0;" :: "n"(N) : "memory");
}

// ---------------- prep: zero h0 + barrier state (every replay) ----------------
__global__ void zero_h_kernel() {
    int i = blockIdx.x * blockDim.x + threadIdx.x;
    if (i < 2 * 2 * 16 * H) ((float*)g_h2)[i] = 0.f;
    if (i < 2 * 8 * 32) ((unsigned*)g_cnt2)[i] = 0u;
}

// ---------------- transpose U [H][4H] -> UT [4H][H] ----------------
__global__ void transpose_u_kernel(const float* __restrict__ U) {
    __shared__ float tile[32][33];
    int x = blockIdx.x * 32 + threadIdx.x;
    int y = blockIdx.y * 32 + threadIdx.y;
    tile[threadIdx.y][threadIdx.x] = U[(size_t)y * G4 + x];
    __syncthreads();
    int ox = blockIdx.y * 32 + threadIdx.x;
    int oy = blockIdx.x * 32 + threadIdx.y;
    g_UT[(size_t)oy * H + ox] = tile[threadIdx.x][threadIdx.y];
}

// ---------------- input GEMM: g_xz = x @ W (f32x2 packed) ----------------
__global__ __launch_bounds__(256) void sgemm_xw_kernel(const float* __restrict__ A,
                                                       const float* __restrict__ Bm) {
    const int K = INDIM, N = G4;
    __shared__ float As[8][128];
    __shared__ float Bs[8][128];
    const int tid = threadIdx.x;
    const int bm = blockIdx.y, bn = blockIdx.x;
    const int arow = tid >> 1, acol = (tid & 1) << 2;
    const int brow = tid >> 5, bcol = (tid & 31) << 2;
    const int tx = tid & 15, ty = tid >> 4;

    unsigned long long acc2[4][8];
#pragma unroll
    for (int i = 0; i < 4; i++)
#pragma unroll
        for (int j = 0; j < 8; j++) acc2[i][j] = 0ull;

    const float* Ap = A + (size_t)(bm * 128 + arow) * K + acol;
    const float* Bp = Bm + (size_t)brow * N + bn * 128 + bcol;

    for (int k0 = 0; k0 < K; k0 += 8) {
        float4 av = *(const float4*)(Ap + k0);
        As[acol + 0][arow] = av.x;
        As[acol + 1][arow] = av.y;
        As[acol + 2][arow] = av.z;
        As[acol + 3][arow] = av.w;
        float4 bv = *(const float4*)(Bp + (size_t)k0 * N);
        *(float4*)&Bs[brow][bcol] = bv;
        __syncthreads();
#pragma unroll
        for (int kk = 0; kk < 8; kk++) {
            ulonglong2 a01 = *(const ulonglong2*)&As[kk][ty * 8];
            ulonglong2 a23 = *(const ulonglong2*)&As[kk][ty * 8 + 4];
            unsigned long long a2[4] = {a01.x, a01.y, a23.x, a23.y};
            float4 b0 = *(const float4*)&Bs[kk][tx * 8];
            float4 b1 = *(const float4*)&Bs[kk][tx * 8 + 4];
            unsigned long long b2[8];
            b2[0] = packdup(b0.x); b2[1] = packdup(b0.y);
            b2[2] = packdup(b0.z); b2[3] = packdup(b0.w);
            b2[4] = packdup(b1.x); b2[5] = packdup(b1.y);
            b2[6] = packdup(b1.z); b2[7] = packdup(b1.w);
#pragma unroll
            for (int i = 0; i < 4; i++)
#pragma unroll
                for (int j = 0; j < 8; j++) fma2(acc2[i][j], a2[i], b2[j]);
        }
        __syncthreads();
    }
    float* Cp = g_xz + (size_t)(bm * 128 + ty * 8) * N + bn * 128 + tx * 8;
#pragma unroll
    for (int i = 0; i < 4; i++) {
        float r0[8], r1[8];
#pragma unroll
        for (int j = 0; j < 8; j++) {
            float x, y;
            asm("mov.b64 {%0, %1}, %2;" : "=f"(x), "=f"(y) : "l"(acc2[i][j]));
            r0[j] = x; r1[j] = y;
        }
        *(float4*)(Cp + (size_t)(2 * i) * N)     = make_float4(r0[0], r0[1], r0[2], r0[3]);
        *(float4*)(Cp + (size_t)(2 * i) * N + 4) = make_float4(r0[4], r0[5], r0[6], r0[7]);
        *(float4*)(Cp + (size_t)(2 * i + 1) * N)     = make_float4(r1[0], r1[1], r1[2], r1[3]);
        *(float4*)(Cp + (size_t)(2 * i + 1) * N + 4) = make_float4(r1[4], r1[5], r1[6], r1[7]);
    }
}

// ---------------- persistent recurrent kernel v11 ----------------
// Two independent 16-batch recurrences (G0, G1), phase-interleaved so each
// group's barrier + staging hides under the other group's compute.
__global__ __launch_bounds__(NTHR3, 1) void lstm_rec11(const float* __restrict__ bias,
                                                       const float* __restrict__ xz,
                                                       float* __restrict__ out) {
    extern __shared__ float sh[];
    // sh_h[grp]: [16][1024] = 64 KB each; zbuf after both
    float* zbuf = sh + 2 * 16 * H;   // [8 warps][4 gates][33]
    const int tid  = threadIdx.x;
    const int lane = tid & 31;
    const int w    = tid >> 5;
    const int u    = blockIdx.x * 8 + w;

    // U slice -> registers (once); shared by both groups
    unsigned long long ur2[4][16];
#pragma unroll
    for (int g = 0; g < 4; g++)
#pragma unroll
        for (int m = 0; m < 8; m++) {
            ulonglong2 v = *(const ulonglong2*)(g_UT + ((size_t)(g * H + u)) * H
                                                + m * 128 + lane * 4);
            ur2[g][2 * m]     = v.x;
            ur2[g][2 * m + 1] = v.y;
        }
    const float b_i = bias[u], b_f = bias[H + u], b_g = bias[2 * H + u], b_o = bias[3 * H + u];
    float cstate[2] = {0.f, 0.f};

    const bool hi4 = (lane & 16) != 0;
    const bool hi3 = (lane & 8) != 0;
    const bool hi2 = (lane & 4) != 0;
    const bool hi1 = (lane & 2) != 0;
    const bool hi0 = (lane & 1) != 0;

    unsigned sh_u32[2];
    {
        unsigned long long a = (unsigned long long)__cvta_generic_to_shared(sh);
        sh_u32[0] = (unsigned)a;
        sh_u32[1] = (unsigned)a + 16 * H * 4;
    }

    // prologue: stage G0(0): 2 chunks x (8 x 16B per thread)
    {
        const float4* src = (const float4*)g_h2[0][0];
#pragma unroll
        for (int chk = 0; chk < 2; chk++) {
#pragma unroll
            for (int k = 0; k < 8; k++) {
                int idx = chk * 2048 + k * 256 + tid;
                cp_async16(sh_u32[0] + idx * 16, src + idx);
            }
            cp_commit();
        }
    }

    for (int t = 0; t < TSTEPS; t++) {
#pragma unroll
        for (int grp = 0; grp < 2; grp++) {
            const int og = grp ^ 1;
            float* sh_g = sh + grp * 16 * H;

            // x prefetch for this group (lane&15 plays batch role)
            const size_t xbase = ((size_t)(grp * 16 + (lane & 15)) * TSTEPS + t)
                                 * (size_t)G4 + u;
            const float x0 = xz[xbase];
            const float x1 = xz[xbase + H];
            const float x2 = xz[xbase + 2 * H];
            const float x3 = xz[xbase + 3 * H];

            // ---- two chunks of 8 batches: accumulate + batched fold ----
#pragma unroll
            for (int chk = 0; chk < 2; chk++) {
                if (chk == 0) cp_wait<1>();
                else cp_wait<0>();
                __syncthreads();

                unsigned long long acc[4][8];
#pragma unroll
                for (int g = 0; g < 4; g++)
#pragma unroll
                    for (int bb = 0; bb < 8; bb++) acc[g][bb] = 0ull;

#pragma unroll
                for (int bb = 0; bb < 8; bb++) {
                    const float* hb = sh_g + (chk * 8 + bb) * H + lane * 4;
#pragma unroll
                    for (int m = 0; m < 8; m++) {
                        ulonglong2 hv = *(const ulonglong2*)(hb + m * 128);
                        fma2(acc[0][bb], hv.x, ur2[0][2 * m]);
                        fma2(acc[1][bb], hv.x, ur2[1][2 * m]);
                        fma2(acc[2][bb], hv.x, ur2[2][2 * m]);
                        fma2(acc[3][bb], hv.x, ur2[3][2 * m]);
                        fma2(acc[0][bb], hv.y, ur2[0][2 * m + 1]);
                        fma2(acc[1][bb], hv.y, ur2[1][2 * m + 1]);
                        fma2(acc[2][bb], hv.y, ur2[2][2 * m + 1]);
                        fma2(acc[3][bb], hv.y, ur2[3][2 * m + 1]);
                    }
                }
                float xr[32];
#pragma unroll
                for (int g = 0; g < 4; g++)
#pragma unroll
                    for (int bb = 0; bb < 8; bb++) xr[g * 8 + bb] = hsum2(acc[g][bb]);
#pragma unroll
                for (int i = 0; i < 16; i++) {
                    float s = hi4 ? xr[i] : xr[i + 16];
                    float r = __shfl_xor_sync(0xffffffffu, s, 16);
                    xr[i] = (hi4 ? xr[i + 16] : xr[i]) + r;
                }
#pragma unroll
                for (int i = 0; i < 8; i++) {
                    float s = hi3 ? xr[i] : xr[i + 8];
                    float r = __shfl_xor_sync(0xffffffffu, s, 8);
                    xr[i] = (hi3 ? xr[i + 8] : xr[i]) + r;
                }
#pragma unroll
                for (int i = 0; i < 4; i++) {
                    float s = hi2 ? xr[i] : xr[i + 4];
                    float r = __shfl_xor_sync(0xffffffffu, s, 4);
                    xr[i] = (hi2 ? xr[i + 4] : xr[i]) + r;
                }
#pragma unroll
                for (int i = 0; i < 2; i++) {
                    float s = hi1 ? xr[i] : xr[i + 2];
                    float r = __shfl_xor_sync(0xffffffffu, s, 2);
                    xr[i] = (hi1 ? xr[i + 2] : xr[i]) + r;
                }
                float v;
                {
                    float s = hi0 ? xr[0] : xr[1];
                    float r = __shfl_xor_sync(0xffffffffu, s, 1);
                    v = (hi0 ? xr[1] : xr[0]) + r;
                }
                zbuf[w * 132 + (lane >> 3) * 33 + chk * 8 + (lane & 7)] = v;
            }

            // ---- poll other group's readiness, then issue its staging ----
            const int t_o = (grp == 0) ? t : t + 1;
            const bool do_o = (grp == 0) || (t < TSTEPS - 1);
            if (do_o) {
                if (t_o > 0) {
                    if (tid < 32) {
                        const unsigned need = (unsigned)t_o * 16u;
                        bool done;
                        do {
                            done = (lane >= 8)
                                   || (ld_cg_u32(&g_cnt2[og][lane * 32]) >= need);
                        } while (!__all_sync(0xffffffffu, done));
                        __threadfence();
                    }
                    __syncthreads();
                }
                const float4* src = (const float4*)g_h2[og][t_o & 1];
#pragma unroll
                for (int chk = 0; chk < 2; chk++) {
#pragma unroll
                    for (int k = 0; k < 8; k++) {
                        int idx = chk * 2048 + k * 256 + tid;
                        cp_async16(sh_u32[og] + idx * 16, src + idx);
                    }
                    cp_commit();
                }
            }

            // ---- pointwise (lanes 0..15 = this group's batches) ----
            __syncwarp();
            if (lane < 16) {
                const int zw = w * 132;
                float zi = zbuf[zw + lane]      + x0 + b_i;
                float zf = zbuf[zw + 33 + lane] + x1 + b_f;
                float zg = zbuf[zw + 66 + lane] + x2 + b_g;
                float zo = zbuf[zw + 99 + lane] + x3 + b_o;

                const float ig = 1.f / (1.f + __expf(-zi));
                const float fg = 1.f / (1.f + __expf(-zf));
                const float gv = tanhf(zg);
                const float og2 = 1.f / (1.f + __expf(-zo));

                cstate[grp] = fg * cstate[grp] + ig * gv;
                const float hval = og2 * tanhf(cstate[grp]);

                out[((size_t)(grp * 16 + lane) * TSTEPS + t) * H + u] = hval;
                g_h2[grp][(t + 1) & 1][lane * H + u] = hval;
            }

            // ---- arrive this group's step t+1 ----
            if (t < TSTEPS - 1) {
                __threadfence();
                __syncthreads();
                if (tid == 0) atomicAdd(&g_cnt2[grp][(blockIdx.x & 7) * 32], 1u);
            }
        }
    }
}

// ---------------- launch ----------------
extern "C" void kernel_launch(void* const* d_in, const int* in_sizes, int n_in,
                              void* d_out, int out_size) {
    const float* x    = (const float*)d_in[0];  // [32,512,512]
    const float* W    = (const float*)d_in[1];  // [512,4096]
    const float* U    = (const float*)d_in[2];  // [1024,4096]
    const float* bias = (const float*)d_in[3];  // [4096]
    float* out = (float*)d_out;                 // [32,512,1024]

    static const int rec_smem = (2 * 16 * H + 8 * 132) * (int)sizeof(float);
    cudaFuncSetAttribute(lstm_rec11, cudaFuncAttributeMaxDynamicSharedMemorySize, rec_smem);

    float* xz_dev = nullptr;
    cudaGetSymbolAddress((void**)&xz_dev, g_xz);

    zero_h_kernel<<<(2 * 2 * 16 * H + 255) / 256, 256>>>();
    transpose_u_kernel<<<dim3(G4 / 32, H / 32), dim3(32, 32)>>>(U);
    sgemm_xw_kernel<<<dim3(G4 / 128, (BATCH * TSTEPS) / 128), 256>>>(x, W);
    lstm_rec11<<<NCTA3, NTHR3, rec_smem>>>(bias, xz_dev, out);
}

// round 13
// speedup vs baseline: 1.1590x; 1.1590x over previous
#include <cuda_runtime.h>
#include <math.h>

#define H      1024
#define BATCH  32
#define TSTEPS 512
#define INDIM  512
#define G4     (4*H)
#define NCTA   128
#define NTHR   256   // 8 warps: warp = (mt, kq)

// ---------------- scratch ----------------
__device__ float g_xz[(size_t)BATCH * TSTEPS * G4];     // 268 MB: x@W, [B*T, 4H]
__device__ float g_Uph[(size_t)NCTA * 2 * 128 * 32 * 4]; // 16 MB: A-frag packed U_hi
__device__ float g_Upl[(size_t)NCTA * 2 * 128 * 32 * 4]; // 16 MB: A-frag packed U_lo
__device__ float g_h[2][H * BATCH];                      // ping-pong h, [u][b]
__device__ unsigned g_bar_cnt[8 * 32];                   // monotonic epoch counters

// ---------------- helpers ----------------
__device__ __forceinline__ void fma2(unsigned long long& d, unsigned long long a,
                                     unsigned long long b) {
    asm("fma.rn.f32x2 %0, %1, %2, %0;" : "+l"(d) : "l"(a), "l"(b));
}
__device__ __forceinline__ unsigned long long packdup(float a) {
    unsigned long long d;
    asm("mov.b64 %0, {%1, %1};" : "=l"(d) : "f"(a));
    return d;
}
__device__ __forceinline__ unsigned ld_cg_u32(const unsigned* p) {
    unsigned v;
    asm volatile("ld.global.cg.u32 %0, [%1];" : "=r"(v) : "l"(p) : "memory");
    return v;
}
__device__ __forceinline__ void cp_async16(unsigned smem_addr, const void* gptr) {
    asm volatile("cp.async.cg.shared.global [%0], [%1], 16;"
                 :: "r"(smem_addr), "l"(gptr) : "memory");
}
__device__ __forceinline__ void cp_commit() {
    asm volatile("cp.async.commit_group;" ::: "memory");
}
template <int N>
__device__ __forceinline__ void cp_wait() {
    asm volatile("cp.async.wait_group %0;" :: "n"(N) : "memory");
}
__device__ __forceinline__ float to_tf32(float x) {
    unsigned r;
    asm("cvt.rna.tf32.f32 %0, %1;" : "=r"(r) : "r"(__float_as_uint(x)));
    return __uint_as_float(r);
}
__device__ __forceinline__ void mma_tf32(float* d, unsigned a0, unsigned a1,
                                         unsigned a2, unsigned a3,
                                         unsigned b0, unsigned b1) {
    asm("mma.sync.aligned.m16n8k8.row.col.f32.tf32.tf32.f32 "
        "{%0,%1,%2,%3}, {%4,%5,%6,%7}, {%8,%9}, {%0,%1,%2,%3};"
        : "+f"(d[0]), "+f"(d[1]), "+f"(d[2]), "+f"(d[3])
        : "r"(a0), "r"(a1), "r"(a2), "r"(a3), "r"(b0), "r"(b1));
}

// ---------------- prep: zero h0 + barrier state (every replay) ----------------
__global__ void zero_h_kernel() {
    int i = blockIdx.x * blockDim.x + threadIdx.x;
    if (i < 2 * H * BATCH) ((float*)g_h)[i] = 0.f;
    if (i < 8 * 32) g_bar_cnt[i] = 0u;
}

// ---------------- pack U into A-fragment layout, split hi/lo ----------------
// Index t = ((cta*2 + mt)*128 + kt)*32 + lane; 4 floats per t (a0..a3).
// a_idx: row += (a_idx&1)*8, col(k) += (a_idx>>1)*4.
// A[m][k]: m = col_local (gate*8+u'), k = recurrent dim. Value = U[k][col4h].
__global__ void pack_u_kernel(const float* __restrict__ U) {
    const unsigned t = blockIdx.x * blockDim.x + threadIdx.x;  // < 1048576
    const int lane = t & 31;
    const int kt   = (t >> 5) & 127;
    const int mt   = (t >> 12) & 1;
    const int cta  = t >> 13;
#pragma unroll
    for (int a = 0; a < 4; a++) {
        int c = mt * 16 + (lane >> 2) + (a & 1) * 8;     // col_local 0..31
        int k = kt * 8 + (lane & 3) + (a >> 1) * 4;
        int col4h = (c >> 3) * H + cta * 8 + (c & 7);
        float v = U[(size_t)k * G4 + col4h];
        float hi = to_tf32(v);
        g_Uph[(size_t)t * 4 + a] = hi;
        g_Upl[(size_t)t * 4 + a] = v - hi;
    }
}

// ---------------- input GEMM: g_xz = x @ W (f32x2 packed) ----------------
__global__ __launch_bounds__(256) void sgemm_xw_kernel(const float* __restrict__ A,
                                                       const float* __restrict__ Bm) {
    const int K = INDIM, N = G4;
    __shared__ float As[8][128];
    __shared__ float Bs[8][128];
    const int tid = threadIdx.x;
    const int bm = blockIdx.y, bn = blockIdx.x;
    const int arow = tid >> 1, acol = (tid & 1) << 2;
    const int brow = tid >> 5, bcol = (tid & 31) << 2;
    const int tx = tid & 15, ty = tid >> 4;

    unsigned long long acc2[4][8];
#pragma unroll
    for (int i = 0; i < 4; i++)
#pragma unroll
        for (int j = 0; j < 8; j++) acc2[i][j] = 0ull;

    const float* Ap = A + (size_t)(bm * 128 + arow) * K + acol;
    const float* Bp = Bm + (size_t)brow * N + bn * 128 + bcol;

    for (int k0 = 0; k0 < K; k0 += 8) {
        float4 av = *(const float4*)(Ap + k0);
        As[acol + 0][arow] = av.x;
        As[acol + 1][arow] = av.y;
        As[acol + 2][arow] = av.z;
        As[acol + 3][arow] = av.w;
        float4 bv = *(const float4*)(Bp + (size_t)k0 * N);
        *(float4*)&Bs[brow][bcol] = bv;
        __syncthreads();
#pragma unroll
        for (int kk = 0; kk < 8; kk++) {
            ulonglong2 a01 = *(const ulonglong2*)&As[kk][ty * 8];
            ulonglong2 a23 = *(const ulonglong2*)&As[kk][ty * 8 + 4];
            unsigned long long a2[4] = {a01.x, a01.y, a23.x, a23.y};
            float4 b0 = *(const float4*)&Bs[kk][tx * 8];
            float4 b1 = *(const float4*)&Bs[kk][tx * 8 + 4];
            unsigned long long b2[8];
            b2[0] = packdup(b0.x); b2[1] = packdup(b0.y);
            b2[2] = packdup(b0.z); b2[3] = packdup(b0.w);
            b2[4] = packdup(b1.x); b2[5] = packdup(b1.y);
            b2[6] = packdup(b1.z); b2[7] = packdup(b1.w);
#pragma unroll
            for (int i = 0; i < 4; i++)
#pragma unroll
                for (int j = 0; j < 8; j++) fma2(acc2[i][j], a2[i], b2[j]);
        }
        __syncthreads();
    }
    float* Cp = g_xz + (size_t)(bm * 128 + ty * 8) * N + bn * 128 + tx * 8;
#pragma unroll
    for (int i = 0; i < 4; i++) {
        float r0[8], r1[8];
#pragma unroll
        for (int j = 0; j < 8; j++) {
            float x, y;
            asm("mov.b64 {%0, %1}, %2;" : "=f"(x), "=f"(y) : "l"(acc2[i][j]));
            r0[j] = x; r1[j] = y;
        }
        *(float4*)(Cp + (size_t)(2 * i) * N)     = make_float4(r0[0], r0[1], r0[2], r0[3]);
        *(float4*)(Cp + (size_t)(2 * i) * N + 4) = make_float4(r0[4], r0[5], r0[6], r0[7]);
        *(float4*)(Cp + (size_t)(2 * i + 1) * N)     = make_float4(r1[0], r1[1], r1[2], r1[3]);
        *(float4*)(Cp + (size_t)(2 * i + 1) * N + 4) = make_float4(r1[4], r1[5], r1[6], r1[7]);
    }
}

// ---------------- persistent recurrent kernel v12: tf32 mma.sync ----------------
// smem: [0,32768) floats: U_hi A-frag pack (128 KB, resident)
//       [32768, 53248): h double buffer, 2 x 256 rows x 40 floats (padded)
//       [53248, 57600): zbuf [kq(4)][col(32)][34]
// Warp w: mt = w>>2, kq = w&3; covers Mtile mt, ktiles == kq (mod 4), all 4 Ntiles.
// z = Uhi*hhi + Uhi*hlo + Ulo*hhi  (2-way tf32 split).
__global__ __launch_bounds__(NTHR, 1) void lstm_rec12(const float* __restrict__ bias,
                                                      const float* __restrict__ xz,
                                                      float* __restrict__ out) {
    extern __shared__ float sh[];
    float* zbuf = sh + 53248;
    const int tid  = threadIdx.x;
    const int lane = tid & 31;
    const int w    = tid >> 5;
    const int mt   = w >> 2;
    const int kq   = w & 3;
    const int cta  = blockIdx.x;
    const int u_g  = cta * 8 + w;            // pointwise unit for this warp

    unsigned sh_u32;
    {
        unsigned long long a = (unsigned long long)__cvta_generic_to_shared(sh);
        sh_u32 = (unsigned)a;
    }
    const unsigned hbuf_u32 = sh_u32 + 32768u * 4u;

    // load U_hi pack into smem (128 KB, once)
    {
        const float4* src = (const float4*)g_Uph + (size_t)cta * 8192;
        float4* dst = (float4*)sh;
        for (int i = tid; i < 8192; i += NTHR) dst[i] = src[i];
    }
    // load U_lo slice into registers: 32 ktiles x 4 floats
    float4 ulo[32];
    {
        const float4* src = (const float4*)g_Upl;
#pragma unroll
        for (int c = 0; c < 4; c++)
#pragma unroll
            for (int j = 0; j < 8; j++) {
                int ktg = c * 32 + j * 4 + kq;
                ulo[c * 8 + j] = src[((size_t)(cta * 2 + mt) * 128 + ktg) * 32 + lane];
            }
    }
    const float b_i = bias[u_g], b_f = bias[H + u_g],
                b_g = bias[2 * H + u_g], b_o = bias[3 * H + u_g];
    float cst = 0.f;
    __syncthreads();   // U_hi smem ready

    // prologue: stage chunks 0,1 of h(0)  (chunk = 256 k-rows, 32 KB -> 40 KB padded)
    {
        const float4* src = (const float4*)g_h[0];
#pragma unroll
        for (int c = 0; c < 2; c++) {
#pragma unroll
            for (int k = 0; k < 8; k++) {
                int i = k * 256 + tid;                     // 0..2047
                cp_async16(hbuf_u32 + (c & 1) * 40960u + (i >> 3) * 160u + (i & 7) * 16u,
                           src + c * 2048 + i);
            }
            cp_commit();
        }
    }

    for (int t = 0; t < TSTEPS; t++) {
        // x prefetch (lane = batch)
        const size_t xb = ((size_t)lane * TSTEPS + t) * (size_t)G4 + u_g;
        const float x0 = xz[xb];
        const float x1 = xz[xb + H];
        const float x2 = xz[xb + 2 * H];
        const float x3 = xz[xb + 3 * H];

        float D[4][4], Dc[4][4];
#pragma unroll
        for (int nt = 0; nt < 4; nt++)
#pragma unroll
            for (int i = 0; i < 4; i++) { D[nt][i] = 0.f; Dc[nt][i] = 0.f; }

        const float4* Ap = (const float4*)sh;

#pragma unroll
        for (int c = 0; c < 4; c++) {
            if (c == 0) cp_wait<1>();
            else if (c == 1) cp_wait<1>();
            else if (c == 2) cp_wait<1>();
            else cp_wait<0>();
            __syncthreads();

            const float* hb = sh + 32768 + (c & 1) * 10240;
#pragma unroll
            for (int j = 0; j < 8; j++) {
                const int ktl = j * 4 + kq;
                const int ktg = c * 32 + ktl;
                float4 ah4 = Ap[(mt * 128 + ktg) * 32 + lane];
                const unsigned a0 = __float_as_uint(ah4.x), a1 = __float_as_uint(ah4.y);
                const unsigned a2 = __float_as_uint(ah4.z), a3 = __float_as_uint(ah4.w);
                float4 al4 = ulo[c * 8 + j];
                const unsigned l0 = __float_as_uint(al4.x), l1 = __float_as_uint(al4.y);
                const unsigned l2 = __float_as_uint(al4.z), l3 = __float_as_uint(al4.w);
                const int kr = ktl * 8 + (lane & 3);
#pragma unroll
                for (int nt = 0; nt < 4; nt++) {
                    const float f0 = hb[kr * 40 + nt * 8 + (lane >> 2)];
                    const float f1 = hb[(kr + 4) * 40 + nt * 8 + (lane >> 2)];
                    const float h0 = to_tf32(f0), h1 = to_tf32(f1);
                    const unsigned bh0 = __float_as_uint(h0), bh1 = __float_as_uint(h1);
                    const unsigned bl0 = __float_as_uint(f0 - h0);
                    const unsigned bl1 = __float_as_uint(f1 - h1);
                    mma_tf32(D[nt],  a0, a1, a2, a3, bh0, bh1);
                    mma_tf32(Dc[nt], a0, a1, a2, a3, bl0, bl1);
                    mma_tf32(Dc[nt], l0, l1, l2, l3, bh0, bh1);
                }
            }
            if (c < 2) {   // issue chunk c+2 after this buffer's data fully consumed
                __syncthreads();
                const float4* src = (const float4*)g_h[t & 1];
#pragma unroll
                for (int k = 0; k < 8; k++) {
                    int i = k * 256 + tid;
                    cp_async16(hbuf_u32 + ((c + 2) & 1) * 40960u
                               + (i >> 3) * 160u + (i & 7) * 16u,
                               src + (c + 2) * 2048 + i);
                }
                cp_commit();
            }
        }

        // write D -> zbuf [kq][col(32)][34]
        {
            const int r0 = mt * 16 + (lane >> 2);
            const int cb = 2 * (lane & 3);
#pragma unroll
            for (int nt = 0; nt < 4; nt++) {
                float z0 = D[nt][0] + Dc[nt][0];
                float z1 = D[nt][1] + Dc[nt][1];
                float z2 = D[nt][2] + Dc[nt][2];
                float z3 = D[nt][3] + Dc[nt][3];
                float* zp = zbuf + (kq * 32 + r0) * 34 + nt * 8 + cb;
                *(float2*)zp = make_float2(z0, z1);
                *(float2*)(zp + 8 * 34) = make_float2(z2, z3);
            }
        }
        __syncthreads();

        // pointwise (warp w = unit u_g, lane = batch)
        float zg4[4];
#pragma unroll
        for (int g = 0; g < 4; g++) {
            const int col = g * 8 + w;
            float s = zbuf[col * 34 + lane];
            s += zbuf[(32 + col) * 34 + lane];
            s += zbuf[(64 + col) * 34 + lane];
            s += zbuf[(96 + col) * 34 + lane];
            zg4[g] = s;
        }
        const float zi = zg4[0] + x0 + b_i;
        const float zf = zg4[1] + x1 + b_f;
        const float zc = zg4[2] + x2 + b_g;
        const float zo = zg4[3] + x3 + b_o;

        const float ig = 1.f / (1.f + __expf(-zi));
        const float fg = 1.f / (1.f + __expf(-zf));
        const float gv = tanhf(zc);
        const float og = 1.f / (1.f + __expf(-zo));

        cst = fg * cst + ig * gv;
        const float hval = og * tanhf(cst);

        out[((size_t)lane * TSTEPS + t) * H + u_g] = hval;
        g_h[(t + 1) & 1][u_g * 32 + lane] = hval;        // [u][b] layout

        if (t == TSTEPS - 1) break;

        // ---- grid barrier: monotonic epoch counters, direct polling ----
        __threadfence();
        __syncthreads();
        const unsigned epoch = (unsigned)(t + 1);
        if (tid == 0) atomicAdd(&g_bar_cnt[(blockIdx.x & 7) * 32], 1u);
        if (tid < 32) {
            const unsigned need = epoch * (NCTA / 8);
            bool done;
            do {
                done = (lane >= 8) || (ld_cg_u32(&g_bar_cnt[lane * 32]) >= need);
            } while (!__all_sync(0xffffffffu, done));
            __threadfence();
        }
        __syncthreads();

        // stage chunks 0,1 of h(t+1)
        {
            const float4* src = (const float4*)g_h[(t + 1) & 1];
#pragma unroll
            for (int c = 0; c < 2; c++) {
#pragma unroll
                for (int k = 0; k < 8; k++) {
                    int i = k * 256 + tid;
                    cp_async16(hbuf_u32 + (c & 1) * 40960u + (i >> 3) * 160u + (i & 7) * 16u,
                               src + c * 2048 + i);
                }
                cp_commit();
            }
        }
    }
}

// ---------------- launch ----------------
extern "C" void kernel_launch(void* const* d_in, const int* in_sizes, int n_in,
                              void* d_out, int out_size) {
    const float* x    = (const float*)d_in[0];  // [32,512,512]
    const float* W    = (const float*)d_in[1];  // [512,4096]
    const float* U    = (const float*)d_in[2];  // [1024,4096]
    const float* bias = (const float*)d_in[3];  // [4096]
    float* out = (float*)d_out;                 // [32,512,1024]

    static const int rec_smem = 57600 * (int)sizeof(float);   // 230400 B
    cudaFuncSetAttribute(lstm_rec12, cudaFuncAttributeMaxDynamicSharedMemorySize, rec_smem);

    float* xz_dev = nullptr;
    cudaGetSymbolAddress((void**)&xz_dev, g_xz);

    zero_h_kernel<<<(2 * H * BATCH + 255) / 256, 256>>>();
    pack_u_kernel<<<4096, 256>>>(U);
    sgemm_xw_kernel<<<dim3(G4 / 128, (BATCH * TSTEPS) / 128), 256>>>(x, W);
    lstm_rec12<<<NCTA, NTHR, rec_smem>>>(bias, xz_dev, out);
}

// round 14
// speedup vs baseline: 1.1653x; 1.0055x over previous
#include <cuda_runtime.h>
#include <math.h>

#define H      1024
#define BATCH  32
#define TSTEPS 512
#define INDIM  512
#define G4     (4*H)
#define NCTA   128
#define NTHR   256   // 8 warps: warp = (mt, kq)

// ---------------- scratch ----------------
__device__ float g_xz[(size_t)BATCH * TSTEPS * G4];      // 268 MB: x@W, [B*T, 4H]
__device__ float g_Uph[(size_t)NCTA * 2 * 128 * 32 * 4]; // 16 MB: A-frag packed U_hi
__device__ float g_h[2][H * BATCH];                      // ping-pong h, [u][b]
__device__ unsigned g_bar_cnt[8 * 32];                   // monotonic epoch counters

// ---------------- helpers ----------------
__device__ __forceinline__ void fma2(unsigned long long& d, unsigned long long a,
                                     unsigned long long b) {
    asm("fma.rn.f32x2 %0, %1, %2, %0;" : "+l"(d) : "l"(a), "l"(b));
}
__device__ __forceinline__ unsigned long long packdup(float a) {
    unsigned long long d;
    asm("mov.b64 %0, {%1, %1};" : "=l"(d) : "f"(a));
    return d;
}
__device__ __forceinline__ unsigned ld_cg_u32(const unsigned* p) {
    unsigned v;
    asm volatile("ld.global.cg.u32 %0, [%1];" : "=r"(v) : "l"(p) : "memory");
    return v;
}
__device__ __forceinline__ void cp_async16(unsigned smem_addr, const void* gptr) {
    asm volatile("cp.async.cg.shared.global [%0], [%1], 16;"
                 :: "r"(smem_addr), "l"(gptr) : "memory");
}
__device__ __forceinline__ void cp_commit() {
    asm volatile("cp.async.commit_group;" ::: "memory");
}
template <int N>
__device__ __forceinline__ void cp_wait() {
    asm volatile("cp.async.wait_group %0;" :: "n"(N) : "memory");
}
__device__ __forceinline__ float to_tf32(float x) {
    unsigned r;
    asm("cvt.rna.tf32.f32 %0, %1;" : "=r"(r) : "r"(__float_as_uint(x)));
    return __uint_as_float(r);
}
__device__ __forceinline__ void mma_tf32(float* d, unsigned a0, unsigned a1,
                                         unsigned a2, unsigned a3,
                                         unsigned b0, unsigned b1) {
    asm("mma.sync.aligned.m16n8k8.row.col.f32.tf32.tf32.f32 "
        "{%0,%1,%2,%3}, {%4,%5,%6,%7}, {%8,%9}, {%0,%1,%2,%3};"
        : "+f"(d[0]), "+f"(d[1]), "+f"(d[2]), "+f"(d[3])
        : "r"(a0), "r"(a1), "r"(a2), "r"(a3), "r"(b0), "r"(b1));
}

// ---------------- prep: zero h0 + barrier state (every replay) ----------------
__global__ void zero_h_kernel() {
    int i = blockIdx.x * blockDim.x + threadIdx.x;
    if (i < 2 * H * BATCH) ((float*)g_h)[i] = 0.f;
    if (i < 8 * 32) g_bar_cnt[i] = 0u;
}

// ---------------- pack U_hi into A-fragment layout ----------------
// t = ((cta*2 + mt)*128 + kt)*32 + lane; 4 floats per t.
// a_idx: row += (a&1)*8, k += (a>>1)*4. A[m][k] = U[k][col4h].
__global__ void pack_u_kernel(const float* __restrict__ U) {
    const unsigned t = blockIdx.x * blockDim.x + threadIdx.x;  // < 1048576
    const int lane = t & 31;
    const int kt   = (t >> 5) & 127;
    const int mt   = (t >> 12) & 1;
    const int cta  = t >> 13;
#pragma unroll
    for (int a = 0; a < 4; a++) {
        int c = mt * 16 + (lane >> 2) + (a & 1) * 8;     // col_local 0..31
        int k = kt * 8 + (lane & 3) + (a >> 1) * 4;
        int col4h = (c >> 3) * H + cta * 8 + (c & 7);
        g_Uph[(size_t)t * 4 + a] = to_tf32(U[(size_t)k * G4 + col4h]);
    }
}

// ---------------- input GEMM: g_xz = x @ W (f32x2 packed) ----------------
__global__ __launch_bounds__(256) void sgemm_xw_kernel(const float* __restrict__ A,
                                                       const float* __restrict__ Bm) {
    const int K = INDIM, N = G4;
    __shared__ float As[8][128];
    __shared__ float Bs[8][128];
    const int tid = threadIdx.x;
    const int bm = blockIdx.y, bn = blockIdx.x;
    const int arow = tid >> 1, acol = (tid & 1) << 2;
    const int brow = tid >> 5, bcol = (tid & 31) << 2;
    const int tx = tid & 15, ty = tid >> 4;

    unsigned long long acc2[4][8];
#pragma unroll
    for (int i = 0; i < 4; i++)
#pragma unroll
        for (int j = 0; j < 8; j++) acc2[i][j] = 0ull;

    const float* Ap = A + (size_t)(bm * 128 + arow) * K + acol;
    const float* Bp = Bm + (size_t)brow * N + bn * 128 + bcol;

    for (int k0 = 0; k0 < K; k0 += 8) {
        float4 av = *(const float4*)(Ap + k0);
        As[acol + 0][arow] = av.x;
        As[acol + 1][arow] = av.y;
        As[acol + 2][arow] = av.z;
        As[acol + 3][arow] = av.w;
        float4 bv = *(const float4*)(Bp + (size_t)k0 * N);
        *(float4*)&Bs[brow][bcol] = bv;
        __syncthreads();
#pragma unroll
        for (int kk = 0; kk < 8; kk++) {
            ulonglong2 a01 = *(const ulonglong2*)&As[kk][ty * 8];
            ulonglong2 a23 = *(const ulonglong2*)&As[kk][ty * 8 + 4];
            unsigned long long a2[4] = {a01.x, a01.y, a23.x, a23.y};
            float4 b0 = *(const float4*)&Bs[kk][tx * 8];
            float4 b1 = *(const float4*)&Bs[kk][tx * 8 + 4];
            unsigned long long b2[8];
            b2[0] = packdup(b0.x); b2[1] = packdup(b0.y);
            b2[2] = packdup(b0.z); b2[3] = packdup(b0.w);
            b2[4] = packdup(b1.x); b2[5] = packdup(b1.y);
            b2[6] = packdup(b1.z); b2[7] = packdup(b1.w);
#pragma unroll
            for (int i = 0; i < 4; i++)
#pragma unroll
                for (int j = 0; j < 8; j++) fma2(acc2[i][j], a2[i], b2[j]);
        }
        __syncthreads();
    }
    float* Cp = g_xz + (size_t)(bm * 128 + ty * 8) * N + bn * 128 + tx * 8;
#pragma unroll
    for (int i = 0; i < 4; i++) {
        float r0[8], r1[8];
#pragma unroll
        for (int j = 0; j < 8; j++) {
            float x, y;
            asm("mov.b64 {%0, %1}, %2;" : "=f"(x), "=f"(y) : "l"(acc2[i][j]));
            r0[j] = x; r1[j] = y;
        }
        *(float4*)(Cp + (size_t)(2 * i) * N)     = make_float4(r0[0], r0[1], r0[2], r0[3]);
        *(float4*)(Cp + (size_t)(2 * i) * N + 4) = make_float4(r0[4], r0[5], r0[6], r0[7]);
        *(float4*)(Cp + (size_t)(2 * i + 1) * N)     = make_float4(r1[0], r1[1], r1[2], r1[3]);
        *(float4*)(Cp + (size_t)(2 * i + 1) * N + 4) = make_float4(r1[4], r1[5], r1[6], r1[7]);
    }
}

// ---------------- persistent recurrent kernel v13: tf32, A in regs ----------------
// smem: [0, 40960) floats: h double buffer, 2 x (512 rows x 40 floats padded)
//       [40960, 45312): zbuf [kq(4)][col(32)][34]
// Warp w: mt=w>>2, kq=w&3. A-frags (U_hi) in registers: ah[32] (128 regs).
// z = Uhi*h_hi + Uhi*h_lo  (U truncated once; h exact via hi/lo split).
__global__ __launch_bounds__(NTHR, 1) void lstm_rec13(const float* __restrict__ bias,
                                                      const float* __restrict__ xz,
                                                      float* __restrict__ out) {
    extern __shared__ float sh[];
    float* zbuf = sh + 40960;
    const int tid  = threadIdx.x;
    const int lane = tid & 31;
    const int w    = tid >> 5;
    const int mt   = w >> 2;
    const int kq   = w & 3;
    const int cta  = blockIdx.x;
    const int u_g  = cta * 8 + w;            // pointwise unit for this warp

    unsigned sh_u32;
    {
        unsigned long long a = (unsigned long long)__cvta_generic_to_shared(sh);
        sh_u32 = (unsigned)a;
    }

    // A-fragments (U_hi) -> registers, once. idx -> ktg = idx*4 + kq.
    float4 ah[32];
    {
        const float4* srcA = (const float4*)g_Uph;
#pragma unroll
        for (int idx = 0; idx < 32; idx++) {
            int ktg = idx * 4 + kq;
            ah[idx] = srcA[((size_t)(cta * 2 + mt) * 128 + ktg) * 32 + lane];
        }
    }
    const float b_i = bias[u_g], b_f = bias[H + u_g],
                b_g = bias[2 * H + u_g], b_o = bias[3 * H + u_g];
    float cst = 0.f;

    // prologue: stage both 512-row chunks of h(0)
    {
        const float4* src = (const float4*)g_h[0];
#pragma unroll
        for (int c = 0; c < 2; c++) {
#pragma unroll
            for (int k = 0; k < 16; k++) {
                int i = k * 256 + tid;                 // 0..4095 float4s
                cp_async16(sh_u32 + (unsigned)c * 81920u + (i >> 3) * 160u + (i & 7) * 16u,
                           src + c * 4096 + i);
            }
            cp_commit();
        }
    }

    for (int t = 0; t < TSTEPS; t++) {
        // x prefetch (lane = batch)
        const size_t xb = ((size_t)lane * TSTEPS + t) * (size_t)G4 + u_g;
        const float x0 = xz[xb];
        const float x1 = xz[xb + H];
        const float x2 = xz[xb + 2 * H];
        const float x3 = xz[xb + 3 * H];

        float D[4][4], Dc[4][4];
#pragma unroll
        for (int nt = 0; nt < 4; nt++)
#pragma unroll
            for (int i = 0; i < 4; i++) { D[nt][i] = 0.f; Dc[nt][i] = 0.f; }

#pragma unroll
        for (int c = 0; c < 2; c++) {
            if (c == 0) cp_wait<1>();
            else cp_wait<0>();
            __syncthreads();

            const float* hb = sh + c * 20480;
#pragma unroll
            for (int j = 0; j < 16; j++) {
                const int idx = c * 16 + j;
                const float4 a4 = ah[idx];
                const unsigned a0 = __float_as_uint(a4.x), a1 = __float_as_uint(a4.y);
                const unsigned a2 = __float_as_uint(a4.z), a3 = __float_as_uint(a4.w);
                const int kr = (j * 4 + kq) * 8 + (lane & 3);   // chunk-local row
#pragma unroll
                for (int nt = 0; nt < 4; nt++) {
                    const float f0 = hb[kr * 40 + nt * 8 + (lane >> 2)];
                    const float f1 = hb[(kr + 4) * 40 + nt * 8 + (lane >> 2)];
                    const float h0 = to_tf32(f0), h1 = to_tf32(f1);
                    mma_tf32(D[nt], a0, a1, a2, a3,
                             __float_as_uint(h0), __float_as_uint(h1));
                    mma_tf32(Dc[nt], a0, a1, a2, a3,
                             __float_as_uint(f0 - h0), __float_as_uint(f1 - h1));
                }
            }
        }

        // write D -> zbuf [kq][col(32)][34]
        {
            const int r0 = mt * 16 + (lane >> 2);
            const int cb = 2 * (lane & 3);
#pragma unroll
            for (int nt = 0; nt < 4; nt++) {
                float z0 = D[nt][0] + Dc[nt][0];
                float z1 = D[nt][1] + Dc[nt][1];
                float z2 = D[nt][2] + Dc[nt][2];
                float z3 = D[nt][3] + Dc[nt][3];
                float* zp = zbuf + (kq * 32 + r0) * 34 + nt * 8 + cb;
                *(float2*)zp = make_float2(z0, z1);
                *(float2*)(zp + 8 * 34) = make_float2(z2, z3);
            }
        }
        __syncthreads();

        // pointwise (warp w = unit u_g, lane = batch)
        float zg4[4];
#pragma unroll
        for (int g = 0; g < 4; g++) {
            const int col = g * 8 + w;
            float s = zbuf[col * 34 + lane];
            s += zbuf[(32 + col) * 34 + lane];
            s += zbuf[(64 + col) * 34 + lane];
            s += zbuf[(96 + col) * 34 + lane];
            zg4[g] = s;
        }
        const float zi = zg4[0] + x0 + b_i;
        const float zf = zg4[1] + x1 + b_f;
        const float zc = zg4[2] + x2 + b_g;
        const float zo = zg4[3] + x3 + b_o;

        const float ig = 1.f / (1.f + __expf(-zi));
        const float fg = 1.f / (1.f + __expf(-zf));
        const float gv = tanhf(zc);
        const float og = 1.f / (1.f + __expf(-zo));

        cst = fg * cst + ig * gv;
        const float hval = og * tanhf(cst);

        out[((size_t)lane * TSTEPS + t) * H + u_g] = hval;
        g_h[(t + 1) & 1][u_g * 32 + lane] = hval;        // [u][b] layout

        if (t == TSTEPS - 1) break;

        // ---- grid barrier: monotonic epoch counters, direct polling ----
        __threadfence();
        __syncthreads();
        const unsigned epoch = (unsigned)(t + 1);
        if (tid == 0) atomicAdd(&g_bar_cnt[(blockIdx.x & 7) * 32], 1u);
        if (tid < 32) {
            const unsigned need = epoch * (NCTA / 8);
            bool done;
            do {
                done = (lane >= 8) || (ld_cg_u32(&g_bar_cnt[lane * 32]) >= need);
            } while (!__all_sync(0xffffffffu, done));
            __threadfence();
        }
        __syncthreads();

        // stage both chunks of h(t+1)
        {
            const float4* src = (const float4*)g_h[(t + 1) & 1];
#pragma unroll
            for (int c = 0; c < 2; c++) {
#pragma unroll
                for (int k = 0; k < 16; k++) {
                    int i = k * 256 + tid;
                    cp_async16(sh_u32 + (unsigned)c * 81920u + (i >> 3) * 160u + (i & 7) * 16u,
                               src + c * 4096 + i);
                }
                cp_commit();
            }
        }
    }
}

// ---------------- launch ----------------
extern "C" void kernel_launch(void* const* d_in, const int* in_sizes, int n_in,
                              void* d_out, int out_size) {
    const float* x    = (const float*)d_in[0];  // [32,512,512]
    const float* W    = (const float*)d_in[1];  // [512,4096]
    const float* U    = (const float*)d_in[2];  // [1024,4096]
    const float* bias = (const float*)d_in[3];  // [4096]
    float* out = (float*)d_out;                 // [32,512,1024]

    static const int rec_smem = 45312 * (int)sizeof(float);   // 181248 B
    cudaFuncSetAttribute(lstm_rec13, cudaFuncAttributeMaxDynamicSharedMemorySize, rec_smem);

    float* xz_dev = nullptr;
    cudaGetSymbolAddress((void**)&xz_dev, g_xz);

    zero_h_kernel<<<(2 * H * BATCH + 255) / 256, 256>>>();
    pack_u_kernel<<<4096, 256>>>(U);
    sgemm_xw_kernel<<<dim3(G4 / 128, (BATCH * TSTEPS) / 128), 256>>>(x, W);
    lstm_rec13<<<NCTA, NTHR, rec_smem>>>(bias, xz_dev, out);
}

// round 15
// speedup vs baseline: 1.3239x; 1.1361x over previous
#include <cuda_runtime.h>
#include <math.h>

#define H      1024
#define BATCH  32
#define TSTEPS 512
#define INDIM  512
#define G4     (4*H)
#define NCTA   128
#define NTHR   256   // 8 warps: warp = (mt, kq)

// ---------------- scratch ----------------
__device__ float g_xz[(size_t)BATCH * TSTEPS * G4];      // 268 MB: x@W, [B*T, 4H]
__device__ float g_Uph[(size_t)NCTA * 2 * 128 * 32 * 4]; // 16 MB: A-frag packed U_hi
__device__ float g_h[2][H * BATCH];                      // ping-pong h, [u][b]
__device__ unsigned g_bar_cnt[8 * 32];                   // monotonic epoch counters

// ---------------- helpers ----------------
__device__ __forceinline__ unsigned ld_cg_u32(const unsigned* p) {
    unsigned v;
    asm volatile("ld.global.cg.u32 %0, [%1];" : "=r"(v) : "l"(p) : "memory");
    return v;
}
__device__ __forceinline__ void cp_async16(unsigned smem_addr, const void* gptr) {
    asm volatile("cp.async.cg.shared.global [%0], [%1], 16;"
                 :: "r"(smem_addr), "l"(gptr) : "memory");
}
__device__ __forceinline__ void cp_commit() {
    asm volatile("cp.async.commit_group;" ::: "memory");
}
template <int N>
__device__ __forceinline__ void cp_wait() {
    asm volatile("cp.async.wait_group %0;" :: "n"(N) : "memory");
}
__device__ __forceinline__ float to_tf32(float x) {
    unsigned r;
    asm("cvt.rna.tf32.f32 %0, %1;" : "=r"(r) : "r"(__float_as_uint(x)));
    return __uint_as_float(r);
}
__device__ __forceinline__ void mma_tf32(float* d, unsigned a0, unsigned a1,
                                         unsigned a2, unsigned a3,
                                         unsigned b0, unsigned b1) {
    asm("mma.sync.aligned.m16n8k8.row.col.f32.tf32.tf32.f32 "
        "{%0,%1,%2,%3}, {%4,%5,%6,%7}, {%8,%9}, {%0,%1,%2,%3};"
        : "+f"(d[0]), "+f"(d[1]), "+f"(d[2]), "+f"(d[3])
        : "r"(a0), "r"(a1), "r"(a2), "r"(a3), "r"(b0), "r"(b1));
}

// ---------------- prep: zero h0 + barrier state (every replay) ----------------
__global__ void zero_h_kernel() {
    int i = blockIdx.x * blockDim.x + threadIdx.x;
    if (i < 2 * H * BATCH) ((float*)g_h)[i] = 0.f;
    if (i < 8 * 32) g_bar_cnt[i] = 0u;
}

// ---------------- pack U_hi into A-fragment layout ----------------
__global__ void pack_u_kernel(const float* __restrict__ U) {
    const unsigned t = blockIdx.x * blockDim.x + threadIdx.x;  // < 1048576
    const int lane = t & 31;
    const int kt   = (t >> 5) & 127;
    const int mt   = (t >> 12) & 1;
    const int cta  = t >> 13;
#pragma unroll
    for (int a = 0; a < 4; a++) {
        int c = mt * 16 + (lane >> 2) + (a & 1) * 8;     // col_local 0..31
        int k = kt * 8 + (lane & 3) + (a >> 1) * 4;
        int col4h = (c >> 3) * H + cta * 8 + (c & 7);
        g_Uph[(size_t)t * 4 + a] = to_tf32(U[(size_t)k * G4 + col4h]);
    }
}

// ---------------- input GEMM: g_xz = x @ W (tf32 tensor cores) ----------------
// xz = W_hi * x_hi + W_hi * x_lo (W truncated once; x exact via hi/lo split).
// CTA tile 128(M) x 128(N), K-step 16, cp.async double buffer.
// 8 warps: wm = w>>2 (2 x 64 rows), wn = w&3 (4 x 32 cols). Warp tile 64x32.
// smem floats: xs[2][128][20] at 0 (pad 20 -> conflict-free A-frag LDS),
//              ws[2][16][136] at 5120 (pad 136 -> conflict-free B-frag LDS).
#define XS_OFF(c) ((c) * 2560)
#define WS_OFF(c) (5120 + (c) * 2176)
__global__ __launch_bounds__(256) void sgemm_tf32_kernel(const float* __restrict__ x,
                                                         const float* __restrict__ Wm) {
    extern __shared__ float sh[];
    const int tid  = threadIdx.x;
    const int lane = tid & 31;
    const int w    = tid >> 5;
    const int wm   = w >> 2;
    const int wn   = w & 3;
    const int bm   = blockIdx.y;
    const int bn   = blockIdx.x;

    unsigned sh_u32;
    {
        unsigned long long a = (unsigned long long)__cvta_generic_to_shared(sh);
        sh_u32 = (unsigned)a;
    }

    auto load_tiles = [&](int ks, int buf) {
        // x tile: 512 float4 slots; slot s: m = s>>2, kq = s&3
#pragma unroll
        for (int r = 0; r < 2; r++) {
            int s = r * 256 + tid;
            int m = s >> 2, kq = s & 3;
            const float* src = x + (size_t)(bm * 128 + m) * INDIM + ks * 16 + kq * 4;
            cp_async16(sh_u32 + (unsigned)(XS_OFF(buf) + m * 20 + kq * 4) * 4u, src);
        }
        // W tile: 512 float4 slots; slot s: k = s>>5, nq = s&31
#pragma unroll
        for (int r = 0; r < 2; r++) {
            int s = r * 256 + tid;
            int k = s >> 5, nq = s & 31;
            const float* src = Wm + (size_t)(ks * 16 + k) * G4 + bn * 128 + nq * 4;
            cp_async16(sh_u32 + (unsigned)(WS_OFF(buf) + k * 136 + nq * 4) * 4u, src);
        }
        cp_commit();
    };

    float acc[4][4][4];   // [mt][nt][frag]
#pragma unroll
    for (int mt = 0; mt < 4; mt++)
#pragma unroll
        for (int nt = 0; nt < 4; nt++)
#pragma unroll
            for (int i = 0; i < 4; i++) acc[mt][nt][i] = 0.f;

    load_tiles(0, 0);

    for (int ks = 0; ks < INDIM / 16; ks++) {
        if (ks + 1 < INDIM / 16) { load_tiles(ks + 1, (ks + 1) & 1); cp_wait<1>(); }
        else cp_wait<0>();
        __syncthreads();

        const float* xs = sh + XS_OFF(ks & 1);
        const float* ws = sh + WS_OFF(ks & 1);

#pragma unroll
        for (int k8 = 0; k8 < 2; k8++) {
            const int kk = k8 * 8 + (lane & 3);
            // B frags (W_hi): 4 nt
            unsigned bf0[4], bf1[4];
#pragma unroll
            for (int nt = 0; nt < 4; nt++) {
                const int n = wn * 32 + nt * 8 + (lane >> 2);
                bf0[nt] = __float_as_uint(to_tf32(ws[kk * 136 + n]));
                bf1[nt] = __float_as_uint(to_tf32(ws[(kk + 4) * 136 + n]));
            }
            // A frags (x hi/lo): 4 mt, then 2 mma per (mt,nt)
#pragma unroll
            for (int mt = 0; mt < 4; mt++) {
                const int row = wm * 64 + mt * 16 + (lane >> 2);
                const float f0 = xs[row * 20 + kk];
                const float f1 = xs[(row + 8) * 20 + kk];
                const float f2 = xs[row * 20 + kk + 4];
                const float f3 = xs[(row + 8) * 20 + kk + 4];
                const float h0 = to_tf32(f0), h1 = to_tf32(f1);
                const float h2 = to_tf32(f2), h3 = to_tf32(f3);
                const unsigned A0 = __float_as_uint(h0), A1 = __float_as_uint(h1);
                const unsigned A2 = __float_as_uint(h2), A3 = __float_as_uint(h3);
                const unsigned L0 = __float_as_uint(f0 - h0), L1 = __float_as_uint(f1 - h1);
                const unsigned L2 = __float_as_uint(f2 - h2), L3 = __float_as_uint(f3 - h3);
#pragma unroll
                for (int nt = 0; nt < 4; nt++) {
                    mma_tf32(acc[mt][nt], A0, A1, A2, A3, bf0[nt], bf1[nt]);
                    mma_tf32(acc[mt][nt], L0, L1, L2, L3, bf0[nt], bf1[nt]);
                }
            }
        }
        __syncthreads();
    }

    // epilogue: C frag (r=lane>>2, c=2*(lane&3)); rows +8 for c2/c3
    const int mrow = bm * 128 + wm * 64 + (lane >> 2);
    const int ncol = bn * 128 + wn * 32 + 2 * (lane & 3);
#pragma unroll
    for (int mt = 0; mt < 4; mt++)
#pragma unroll
        for (int nt = 0; nt < 4; nt++) {
            float* p0 = g_xz + (size_t)(mrow + mt * 16) * G4 + ncol + nt * 8;
            float* p1 = g_xz + (size_t)(mrow + mt * 16 + 8) * G4 + ncol + nt * 8;
            *(float2*)p0 = make_float2(acc[mt][nt][0], acc[mt][nt][1]);
            *(float2*)p1 = make_float2(acc[mt][nt][2], acc[mt][nt][3]);
        }
}

// ---------------- persistent recurrent kernel v13 (unchanged, proven) ----------------
__global__ __launch_bounds__(NTHR, 1) void lstm_rec13(const float* __restrict__ bias,
                                                      const float* __restrict__ xz,
                                                      float* __restrict__ out) {
    extern __shared__ float sh[];
    float* zbuf = sh + 40960;
    const int tid  = threadIdx.x;
    const int lane = tid & 31;
    const int w    = tid >> 5;
    const int mt   = w >> 2;
    const int kq   = w & 3;
    const int cta  = blockIdx.x;
    const int u_g  = cta * 8 + w;

    unsigned sh_u32;
    {
        unsigned long long a = (unsigned long long)__cvta_generic_to_shared(sh);
        sh_u32 = (unsigned)a;
    }

    float4 ah[32];
    {
        const float4* srcA = (const float4*)g_Uph;
#pragma unroll
        for (int idx = 0; idx < 32; idx++) {
            int ktg = idx * 4 + kq;
            ah[idx] = srcA[((size_t)(cta * 2 + mt) * 128 + ktg) * 32 + lane];
        }
    }
    const float b_i = bias[u_g], b_f = bias[H + u_g],
                b_g = bias[2 * H + u_g], b_o = bias[3 * H + u_g];
    float cst = 0.f;

    {
        const float4* src = (const float4*)g_h[0];
#pragma unroll
        for (int c = 0; c < 2; c++) {
#pragma unroll
            for (int k = 0; k < 16; k++) {
                int i = k * 256 + tid;
                cp_async16(sh_u32 + (unsigned)c * 81920u + (i >> 3) * 160u + (i & 7) * 16u,
                           src + c * 4096 + i);
            }
            cp_commit();
        }
    }

    for (int t = 0; t < TSTEPS; t++) {
        const size_t xb = ((size_t)lane * TSTEPS + t) * (size_t)G4 + u_g;
        const float x0 = xz[xb];
        const float x1 = xz[xb + H];
        const float x2 = xz[xb + 2 * H];
        const float x3 = xz[xb + 3 * H];

        float D[4][4], Dc[4][4];
#pragma unroll
        for (int nt = 0; nt < 4; nt++)
#pragma unroll
            for (int i = 0; i < 4; i++) { D[nt][i] = 0.f; Dc[nt][i] = 0.f; }

#pragma unroll
        for (int c = 0; c < 2; c++) {
            if (c == 0) cp_wait<1>();
            else cp_wait<0>();
            __syncthreads();

            const float* hb = sh + c * 20480;
#pragma unroll
            for (int j = 0; j < 16; j++) {
                const int idx = c * 16 + j;
                const float4 a4 = ah[idx];
                const unsigned a0 = __float_as_uint(a4.x), a1 = __float_as_uint(a4.y);
                const unsigned a2 = __float_as_uint(a4.z), a3 = __float_as_uint(a4.w);
                const int kr = (j * 4 + kq) * 8 + (lane & 3);
#pragma unroll
                for (int nt = 0; nt < 4; nt++) {
                    const float f0 = hb[kr * 40 + nt * 8 + (lane >> 2)];
                    const float f1 = hb[(kr + 4) * 40 + nt * 8 + (lane >> 2)];
                    const float h0 = to_tf32(f0), h1 = to_tf32(f1);
                    mma_tf32(D[nt], a0, a1, a2, a3,
                             __float_as_uint(h0), __float_as_uint(h1));
                    mma_tf32(Dc[nt], a0, a1, a2, a3,
                             __float_as_uint(f0 - h0), __float_as_uint(f1 - h1));
                }
            }
        }

        {
            const int r0 = mt * 16 + (lane >> 2);
            const int cb = 2 * (lane & 3);
#pragma unroll
            for (int nt = 0; nt < 4; nt++) {
                float z0 = D[nt][0] + Dc[nt][0];
                float z1 = D[nt][1] + Dc[nt][1];
                float z2 = D[nt][2] + Dc[nt][2];
                float z3 = D[nt][3] + Dc[nt][3];
                float* zp = zbuf + (kq * 32 + r0) * 34 + nt * 8 + cb;
                *(float2*)zp = make_float2(z0, z1);
                *(float2*)(zp + 8 * 34) = make_float2(z2, z3);
            }
        }
        __syncthreads();

        float zg4[4];
#pragma unroll
        for (int g = 0; g < 4; g++) {
            const int col = g * 8 + w;
            float s = zbuf[col * 34 + lane];
            s += zbuf[(32 + col) * 34 + lane];
            s += zbuf[(64 + col) * 34 + lane];
            s += zbuf[(96 + col) * 34 + lane];
            zg4[g] = s;
        }
        const float zi = zg4[0] + x0 + b_i;
        const float zf = zg4[1] + x1 + b_f;
        const float zc = zg4[2] + x2 + b_g;
        const float zo = zg4[3] + x3 + b_o;

        const float ig = 1.f / (1.f + __expf(-zi));
        const float fg = 1.f / (1.f + __expf(-zf));
        const float gv = tanhf(zc);
        const float og = 1.f / (1.f + __expf(-zo));

        cst = fg * cst + ig * gv;
        const float hval = og * tanhf(cst);

        out[((size_t)lane * TSTEPS + t) * H + u_g] = hval;
        g_h[(t + 1) & 1][u_g * 32 + lane] = hval;

        if (t == TSTEPS - 1) break;

        __threadfence();
        __syncthreads();
        const unsigned epoch = (unsigned)(t + 1);
        if (tid == 0) atomicAdd(&g_bar_cnt[(blockIdx.x & 7) * 32], 1u);
        if (tid < 32) {
            const unsigned need = epoch * (NCTA / 8);
            bool done;
            do {
                done = (lane >= 8) || (ld_cg_u32(&g_bar_cnt[lane * 32]) >= need);
            } while (!__all_sync(0xffffffffu, done));
            __threadfence();
        }
        __syncthreads();

        {
            const float4* src = (const float4*)g_h[(t + 1) & 1];
#pragma unroll
            for (int c = 0; c < 2; c++) {
#pragma unroll
                for (int k = 0; k < 16; k++) {
                    int i = k * 256 + tid;
                    cp_async16(sh_u32 + (unsigned)c * 81920u + (i >> 3) * 160u + (i & 7) * 16u,
                               src + c * 4096 + i);
                }
                cp_commit();
            }
        }
    }
}

// ---------------- launch ----------------
extern "C" void kernel_launch(void* const* d_in, const int* in_sizes, int n_in,
                              void* d_out, int out_size) {
    const float* x    = (const float*)d_in[0];  // [32,512,512]
    const float* W    = (const float*)d_in[1];  // [512,4096]
    const float* U    = (const float*)d_in[2];  // [1024,4096]
    const float* bias = (const float*)d_in[3];  // [4096]
    float* out = (float*)d_out;                 // [32,512,1024]

    static const int rec_smem  = 45312 * (int)sizeof(float);   // 181248 B
    static const int gemm_smem = 9472 * (int)sizeof(float);    // 37888 B
    cudaFuncSetAttribute(lstm_rec13, cudaFuncAttributeMaxDynamicSharedMemorySize, rec_smem);
    cudaFuncSetAttribute(sgemm_tf32_kernel, cudaFuncAttributeMaxDynamicSharedMemorySize,
                         gemm_smem);

    float* xz_dev = nullptr;
    cudaGetSymbolAddress((void**)&xz_dev, g_xz);

    zero_h_kernel<<<(2 * H * BATCH + 255) / 256, 256>>>();
    pack_u_kernel<<<4096, 256>>>(U);
    sgemm_tf32_kernel<<<dim3(G4 / 128, (BATCH * TSTEPS) / 128), 256, gemm_smem>>>(x, W);
    lstm_rec13<<<NCTA, NTHR, rec_smem>>>(bias, xz_dev, out);
}

// round 16
// speedup vs baseline: 1.6324x; 1.2330x over previous
#include <cuda_runtime.h>
#include <math.h>

#define H      1024
#define BATCH  32
#define TSTEPS 512
#define INDIM  512
#define G4     (4*H)
#define NCTA   128
#define NTHR   256   // 8 warps: warp = (mt, kq)

// ---------------- scratch ----------------
__device__ float g_xz[(size_t)BATCH * TSTEPS * G4];      // 268 MB: x@W, [B*T, 4H]
__device__ float g_Uph[(size_t)NCTA * 2 * 128 * 32 * 4]; // 16 MB: A-frag packed U_hi
__device__ float g_h[2][H * BATCH];                      // ping-pong h (tf32-rounded), [u][b]
__device__ unsigned g_bar_cnt[8 * 32];                   // monotonic epoch counters

// ---------------- helpers ----------------
__device__ __forceinline__ unsigned ld_cg_u32(const unsigned* p) {
    unsigned v;
    asm volatile("ld.global.cg.u32 %0, [%1];" : "=r"(v) : "l"(p) : "memory");
    return v;
}
__device__ __forceinline__ void cp_async16(unsigned smem_addr, const void* gptr) {
    asm volatile("cp.async.cg.shared.global [%0], [%1], 16;"
                 :: "r"(smem_addr), "l"(gptr) : "memory");
}
__device__ __forceinline__ void cp_commit() {
    asm volatile("cp.async.commit_group;" ::: "memory");
}
template <int N>
__device__ __forceinline__ void cp_wait() {
    asm volatile("cp.async.wait_group %0;" :: "n"(N) : "memory");
}
__device__ __forceinline__ float to_tf32(float x) {
    unsigned r;
    asm("cvt.rna.tf32.f32 %0, %1;" : "=r"(r) : "r"(__float_as_uint(x)));
    return __uint_as_float(r);
}
__device__ __forceinline__ void mma_tf32(float* d, unsigned a0, unsigned a1,
                                         unsigned a2, unsigned a3,
                                         unsigned b0, unsigned b1) {
    asm("mma.sync.aligned.m16n8k8.row.col.f32.tf32.tf32.f32 "
        "{%0,%1,%2,%3}, {%4,%5,%6,%7}, {%8,%9}, {%0,%1,%2,%3};"
        : "+f"(d[0]), "+f"(d[1]), "+f"(d[2]), "+f"(d[3])
        : "r"(a0), "r"(a1), "r"(a2), "r"(a3), "r"(b0), "r"(b1));
}

// ---------------- prep: zero h0 + barrier state (every replay) ----------------
__global__ void zero_h_kernel() {
    int i = blockIdx.x * blockDim.x + threadIdx.x;
    if (i < 2 * H * BATCH) ((float*)g_h)[i] = 0.f;
    if (i < 8 * 32) g_bar_cnt[i] = 0u;
}

// ---------------- pack U_hi into A-fragment layout ----------------
__global__ void pack_u_kernel(const float* __restrict__ U) {
    const unsigned t = blockIdx.x * blockDim.x + threadIdx.x;  // < 1048576
    const int lane = t & 31;
    const int kt   = (t >> 5) & 127;
    const int mt   = (t >> 12) & 1;
    const int cta  = t >> 13;
#pragma unroll
    for (int a = 0; a < 4; a++) {
        int c = mt * 16 + (lane >> 2) + (a & 1) * 8;     // col_local 0..31
        int k = kt * 8 + (lane & 3) + (a >> 1) * 4;
        int col4h = (c >> 3) * H + cta * 8 + (c & 7);
        g_Uph[(size_t)t * 4 + a] = to_tf32(U[(size_t)k * G4 + col4h]);
    }
}

// ---------------- input GEMM: g_xz = x @ W (tf32 tensor cores) ----------------
// xz = W_hi * x_hi + W_hi * x_lo (W truncated once; x exact via hi/lo split).
#define XS_OFF(c) ((c) * 2560)
#define WS_OFF(c) (5120 + (c) * 2176)
__global__ __launch_bounds__(256) void sgemm_tf32_kernel(const float* __restrict__ x,
                                                         const float* __restrict__ Wm) {
    extern __shared__ float sh[];
    const int tid  = threadIdx.x;
    const int lane = tid & 31;
    const int w    = tid >> 5;
    const int wm   = w >> 2;
    const int wn   = w & 3;
    const int bm   = blockIdx.y;
    const int bn   = blockIdx.x;

    unsigned sh_u32;
    {
        unsigned long long a = (unsigned long long)__cvta_generic_to_shared(sh);
        sh_u32 = (unsigned)a;
    }

    auto load_tiles = [&](int ks, int buf) {
#pragma unroll
        for (int r = 0; r < 2; r++) {
            int s = r * 256 + tid;
            int m = s >> 2, kq = s & 3;
            const float* src = x + (size_t)(bm * 128 + m) * INDIM + ks * 16 + kq * 4;
            cp_async16(sh_u32 + (unsigned)(XS_OFF(buf) + m * 20 + kq * 4) * 4u, src);
        }
#pragma unroll
        for (int r = 0; r < 2; r++) {
            int s = r * 256 + tid;
            int k = s >> 5, nq = s & 31;
            const float* src = Wm + (size_t)(ks * 16 + k) * G4 + bn * 128 + nq * 4;
            cp_async16(sh_u32 + (unsigned)(WS_OFF(buf) + k * 136 + nq * 4) * 4u, src);
        }
        cp_commit();
    };

    float acc[4][4][4];
#pragma unroll
    for (int mt = 0; mt < 4; mt++)
#pragma unroll
        for (int nt = 0; nt < 4; nt++)
#pragma unroll
            for (int i = 0; i < 4; i++) acc[mt][nt][i] = 0.f;

    load_tiles(0, 0);

    for (int ks = 0; ks < INDIM / 16; ks++) {
        if (ks + 1 < INDIM / 16) { load_tiles(ks + 1, (ks + 1) & 1); cp_wait<1>(); }
        else cp_wait<0>();
        __syncthreads();

        const float* xs = sh + XS_OFF(ks & 1);
        const float* ws = sh + WS_OFF(ks & 1);

#pragma unroll
        for (int k8 = 0; k8 < 2; k8++) {
            const int kk = k8 * 8 + (lane & 3);
            unsigned bf0[4], bf1[4];
#pragma unroll
            for (int nt = 0; nt < 4; nt++) {
                const int n = wn * 32 + nt * 8 + (lane >> 2);
                bf0[nt] = __float_as_uint(to_tf32(ws[kk * 136 + n]));
                bf1[nt] = __float_as_uint(to_tf32(ws[(kk + 4) * 136 + n]));
            }
#pragma unroll
            for (int mt = 0; mt < 4; mt++) {
                const int row = wm * 64 + mt * 16 + (lane >> 2);
                const float f0 = xs[row * 20 + kk];
                const float f1 = xs[(row + 8) * 20 + kk];
                const float f2 = xs[row * 20 + kk + 4];
                const float f3 = xs[(row + 8) * 20 + kk + 4];
                const float h0 = to_tf32(f0), h1 = to_tf32(f1);
                const float h2 = to_tf32(f2), h3 = to_tf32(f3);
                const unsigned A0 = __float_as_uint(h0), A1 = __float_as_uint(h1);
                const unsigned A2 = __float_as_uint(h2), A3 = __float_as_uint(h3);
                const unsigned L0 = __float_as_uint(f0 - h0), L1 = __float_as_uint(f1 - h1);
                const unsigned L2 = __float_as_uint(f2 - h2), L3 = __float_as_uint(f3 - h3);
#pragma unroll
                for (int nt = 0; nt < 4; nt++) {
                    mma_tf32(acc[mt][nt], A0, A1, A2, A3, bf0[nt], bf1[nt]);
                    mma_tf32(acc[mt][nt], L0, L1, L2, L3, bf0[nt], bf1[nt]);
                }
            }
        }
        __syncthreads();
    }

    const int mrow = bm * 128 + wm * 64 + (lane >> 2);
    const int ncol = bn * 128 + wn * 32 + 2 * (lane & 3);
#pragma unroll
    for (int mt = 0; mt < 4; mt++)
#pragma unroll
        for (int nt = 0; nt < 4; nt++) {
            float* p0 = g_xz + (size_t)(mrow + mt * 16) * G4 + ncol + nt * 8;
            float* p1 = g_xz + (size_t)(mrow + mt * 16 + 8) * G4 + ncol + nt * 8;
            *(float2*)p0 = make_float2(acc[mt][nt][0], acc[mt][nt][1]);
            *(float2*)p1 = make_float2(acc[mt][nt][2], acc[mt][nt][3]);
        }
}

// ---------------- persistent recurrent kernel v15: single-mma tf32 ----------------
// g_h stores tf32-rounded h, so B frags are bare LDS (no cvt/sub) and the
// correction mma stream is gone: 128 mma/warp/step.
__global__ __launch_bounds__(NTHR, 1) void lstm_rec15(const float* __restrict__ bias,
                                                      const float* __restrict__ xz,
                                                      float* __restrict__ out) {
    extern __shared__ float sh[];
    float* zbuf = sh + 40960;
    const int tid  = threadIdx.x;
    const int lane = tid & 31;
    const int w    = tid >> 5;
    const int mt   = w >> 2;
    const int kq   = w & 3;
    const int cta  = blockIdx.x;
    const int u_g  = cta * 8 + w;

    unsigned sh_u32;
    {
        unsigned long long a = (unsigned long long)__cvta_generic_to_shared(sh);
        sh_u32 = (unsigned)a;
    }

    float4 ah[32];
    {
        const float4* srcA = (const float4*)g_Uph;
#pragma unroll
        for (int idx = 0; idx < 32; idx++) {
            int ktg = idx * 4 + kq;
            ah[idx] = srcA[((size_t)(cta * 2 + mt) * 128 + ktg) * 32 + lane];
        }
    }
    const float b_i = bias[u_g], b_f = bias[H + u_g],
                b_g = bias[2 * H + u_g], b_o = bias[3 * H + u_g];
    float cst = 0.f;

    {
        const float4* src = (const float4*)g_h[0];
#pragma unroll
        for (int c = 0; c < 2; c++) {
#pragma unroll
            for (int k = 0; k < 16; k++) {
                int i = k * 256 + tid;
                cp_async16(sh_u32 + (unsigned)c * 81920u + (i >> 3) * 160u + (i & 7) * 16u,
                           src + c * 4096 + i);
            }
            cp_commit();
        }
    }

    for (int t = 0; t < TSTEPS; t++) {
        const size_t xb = ((size_t)lane * TSTEPS + t) * (size_t)G4 + u_g;
        const float x0 = xz[xb];
        const float x1 = xz[xb + H];
        const float x2 = xz[xb + 2 * H];
        const float x3 = xz[xb + 3 * H];

        float D[4][4];
#pragma unroll
        for (int nt = 0; nt < 4; nt++)
#pragma unroll
            for (int i = 0; i < 4; i++) D[nt][i] = 0.f;

#pragma unroll
        for (int c = 0; c < 2; c++) {
            if (c == 0) cp_wait<1>();
            else cp_wait<0>();
            __syncthreads();

            const float* hb = sh + c * 20480;
#pragma unroll
            for (int j = 0; j < 16; j++) {
                const int idx = c * 16 + j;
                const float4 a4 = ah[idx];
                const unsigned a0 = __float_as_uint(a4.x), a1 = __float_as_uint(a4.y);
                const unsigned a2 = __float_as_uint(a4.z), a3 = __float_as_uint(a4.w);
                const int kr = (j * 4 + kq) * 8 + (lane & 3);
#pragma unroll
                for (int nt = 0; nt < 4; nt++) {
                    const unsigned b0 =
                        __float_as_uint(hb[kr * 40 + nt * 8 + (lane >> 2)]);
                    const unsigned b1 =
                        __float_as_uint(hb[(kr + 4) * 40 + nt * 8 + (lane >> 2)]);
                    mma_tf32(D[nt], a0, a1, a2, a3, b0, b1);
                }
            }
        }

        {
            const int r0 = mt * 16 + (lane >> 2);
            const int cb = 2 * (lane & 3);
#pragma unroll
            for (int nt = 0; nt < 4; nt++) {
                float* zp = zbuf + (kq * 32 + r0) * 34 + nt * 8 + cb;
                *(float2*)zp = make_float2(D[nt][0], D[nt][1]);
                *(float2*)(zp + 8 * 34) = make_float2(D[nt][2], D[nt][3]);
            }
        }
        __syncthreads();

        float zg4[4];
#pragma unroll
        for (int g = 0; g < 4; g++) {
            const int col = g * 8 + w;
            float s = zbuf[col * 34 + lane];
            s += zbuf[(32 + col) * 34 + lane];
            s += zbuf[(64 + col) * 34 + lane];
            s += zbuf[(96 + col) * 34 + lane];
            zg4[g] = s;
        }
        const float zi = zg4[0] + x0 + b_i;
        const float zf = zg4[1] + x1 + b_f;
        const float zc = zg4[2] + x2 + b_g;
        const float zo = zg4[3] + x3 + b_o;

        const float ig = 1.f / (1.f + __expf(-zi));
        const float fg = 1.f / (1.f + __expf(-zf));
        const float gv = tanhf(zc);
        const float og = 1.f / (1.f + __expf(-zo));

        cst = fg * cst + ig * gv;
        const float hval = og * tanhf(cst);

        out[((size_t)lane * TSTEPS + t) * H + u_g] = hval;
        g_h[(t + 1) & 1][u_g * 32 + lane] = to_tf32(hval);   // tf32 at the source

        if (t == TSTEPS - 1) break;

        __threadfence();
        __syncthreads();
        const unsigned epoch = (unsigned)(t + 1);
        if (tid == 0) atomicAdd(&g_bar_cnt[(blockIdx.x & 7) * 32], 1u);
        if (tid < 32) {
            const unsigned need = epoch * (NCTA / 8);
            bool done;
            do {
                done = (lane >= 8) || (ld_cg_u32(&g_bar_cnt[lane * 32]) >= need);
            } while (!__all_sync(0xffffffffu, done));
            __threadfence();
        }
        __syncthreads();

        {
            const float4* src = (const float4*)g_h[(t + 1) & 1];
#pragma unroll
            for (int c = 0; c < 2; c++) {
#pragma unroll
                for (int k = 0; k < 16; k++) {
                    int i = k * 256 + tid;
                    cp_async16(sh_u32 + (unsigned)c * 81920u + (i >> 3) * 160u + (i & 7) * 16u,
                               src + c * 4096 + i);
                }
                cp_commit();
            }
        }
    }
}

// ---------------- launch ----------------
extern "C" void kernel_launch(void* const* d_in, const int* in_sizes, int n_in,
                              void* d_out, int out_size) {
    const float* x    = (const float*)d_in[0];  // [32,512,512]
    const float* W    = (const float*)d_in[1];  // [512,4096]
    const float* U    = (const float*)d_in[2];  // [1024,4096]
    const float* bias = (const float*)d_in[3];  // [4096]
    float* out = (float*)d_out;                 // [32,512,1024]

    static const int rec_smem  = 45312 * (int)sizeof(float);   // 181248 B
    static const int gemm_smem = 9472 * (int)sizeof(float);    // 37888 B
    cudaFuncSetAttribute(lstm_rec15, cudaFuncAttributeMaxDynamicSharedMemorySize, rec_smem);
    cudaFuncSetAttribute(sgemm_tf32_kernel, cudaFuncAttributeMaxDynamicSharedMemorySize,
                         gemm_smem);

    float* xz_dev = nullptr;
    cudaGetSymbolAddress((void**)&xz_dev, g_xz);

    zero_h_kernel<<<(2 * H * BATCH + 255) / 256, 256>>>();
    pack_u_kernel<<<4096, 256>>>(U);
    sgemm_tf32_kernel<<<dim3(G4 / 128, (BATCH * TSTEPS) / 128), 256, gemm_smem>>>(x, W);
    lstm_rec15<<<NCTA, NTHR, rec_smem>>>(bias, xz_dev, out);
}

// round 17
// speedup vs baseline: 1.8773x; 1.1500x over previous
#include <cuda_runtime.h>
#include <cuda_fp16.h>
#include <math.h>

#define H      1024
#define BATCH  32
#define TSTEPS 512
#define INDIM  512
#define G4     (4*H)
#define NCTA   128
#define NTHR   256   // 8 warps: warp = (mt, kq)

// ---------------- scratch ----------------
__device__ float    g_xz[(size_t)BATCH * TSTEPS * G4];        // 268 MB: x@W
__device__ unsigned g_Uph16[(size_t)NCTA * 2 * 64 * 32 * 4];  // 8 MB: A-frag packed U fp16
__device__ __half   g_h16[2][BATCH * H];                      // ping-pong h fp16, [b][u]
__device__ unsigned g_bar_cnt[8 * 32];                        // monotonic epoch counters

// ---------------- helpers ----------------
__device__ __forceinline__ unsigned ld_cg_u32(const unsigned* p) {
    unsigned v;
    asm volatile("ld.global.cg.u32 %0, [%1];" : "=r"(v) : "l"(p) : "memory");
    return v;
}
__device__ __forceinline__ void cp_async16(unsigned smem_addr, const void* gptr) {
    asm volatile("cp.async.cg.shared.global [%0], [%1], 16;"
                 :: "r"(smem_addr), "l"(gptr) : "memory");
}
__device__ __forceinline__ void cp_commit() {
    asm volatile("cp.async.commit_group;" ::: "memory");
}
template <int N>
__device__ __forceinline__ void cp_wait() {
    asm volatile("cp.async.wait_group %0;" :: "n"(N) : "memory");
}
__device__ __forceinline__ float to_tf32(float x) {
    unsigned r;
    asm("cvt.rna.tf32.f32 %0, %1;" : "=r"(r) : "r"(__float_as_uint(x)));
    return __uint_as_float(r);
}
__device__ __forceinline__ void mma_tf32(float* d, unsigned a0, unsigned a1,
                                         unsigned a2, unsigned a3,
                                         unsigned b0, unsigned b1) {
    asm("mma.sync.aligned.m16n8k8.row.col.f32.tf32.tf32.f32 "
        "{%0,%1,%2,%3}, {%4,%5,%6,%7}, {%8,%9}, {%0,%1,%2,%3};"
        : "+f"(d[0]), "+f"(d[1]), "+f"(d[2]), "+f"(d[3])
        : "r"(a0), "r"(a1), "r"(a2), "r"(a3), "r"(b0), "r"(b1));
}
__device__ __forceinline__ void mma_f16(float* d, unsigned a0, unsigned a1,
                                        unsigned a2, unsigned a3,
                                        unsigned b0, unsigned b1) {
    asm("mma.sync.aligned.m16n8k16.row.col.f32.f16.f16.f32 "
        "{%0,%1,%2,%3}, {%4,%5,%6,%7}, {%8,%9}, {%0,%1,%2,%3};"
        : "+f"(d[0]), "+f"(d[1]), "+f"(d[2]), "+f"(d[3])
        : "r"(a0), "r"(a1), "r"(a2), "r"(a3), "r"(b0), "r"(b1));
}

// ---------------- prep: zero h0 + barrier state (every replay) ----------------
__global__ void zero_h_kernel() {
    int i = blockIdx.x * blockDim.x + threadIdx.x;
    if (i < 2 * BATCH * H / 2) ((unsigned*)g_h16)[i] = 0u;   // 2 halves per u32
    if (i < 8 * 32) g_bar_cnt[i] = 0u;
}

// ---------------- pack U into fp16 A-fragment layout (m16n8k16) ----------------
// t = ((cta*2 + mt)*64 + kt)*32 + lane; 4 uints (a0..a3), each = 2 halves (k, k+1).
// a: row c += (a&1)*8, k += (a>>1)*8.  A[m][k] = U[k][col4h(m)].
__global__ void pack_u16_kernel(const float* __restrict__ U) {
    const unsigned t = blockIdx.x * blockDim.x + threadIdx.x;  // < 524288
    const int lane = t & 31;
    const int kt   = (t >> 5) & 63;
    const int mt   = (t >> 11) & 1;
    const int cta  = t >> 12;
#pragma unroll
    for (int a = 0; a < 4; a++) {
        int c  = mt * 16 + (lane >> 2) + (a & 1) * 8;       // col_local 0..31
        int k0 = kt * 16 + 2 * (lane & 3) + (a >> 1) * 8;
        int col4h = (c >> 3) * H + cta * 8 + (c & 7);
        __half2 p = __floats2half2_rn(U[(size_t)k0 * G4 + col4h],
                                      U[(size_t)(k0 + 1) * G4 + col4h]);
        g_Uph16[(size_t)t * 4 + a] = *(unsigned*)&p;
    }
}

// ---------------- input GEMM: g_xz = x @ W (tf32, proven) ----------------
#define XS_OFF(c) ((c) * 2560)
#define WS_OFF(c) (5120 + (c) * 2176)
__global__ __launch_bounds__(256) void sgemm_tf32_kernel(const float* __restrict__ x,
                                                         const float* __restrict__ Wm) {
    extern __shared__ float sh[];
    const int tid  = threadIdx.x;
    const int lane = tid & 31;
    const int w    = tid >> 5;
    const int wm   = w >> 2;
    const int wn   = w & 3;
    const int bm   = blockIdx.y;
    const int bn   = blockIdx.x;

    unsigned sh_u32;
    {
        unsigned long long a = (unsigned long long)__cvta_generic_to_shared(sh);
        sh_u32 = (unsigned)a;
    }

    auto load_tiles = [&](int ks, int buf) {
#pragma unroll
        for (int r = 0; r < 2; r++) {
            int s = r * 256 + tid;
            int m = s >> 2, kq = s & 3;
            const float* src = x + (size_t)(bm * 128 + m) * INDIM + ks * 16 + kq * 4;
            cp_async16(sh_u32 + (unsigned)(XS_OFF(buf) + m * 20 + kq * 4) * 4u, src);
        }
#pragma unroll
        for (int r = 0; r < 2; r++) {
            int s = r * 256 + tid;
            int k = s >> 5, nq = s & 31;
            const float* src = Wm + (size_t)(ks * 16 + k) * G4 + bn * 128 + nq * 4;
            cp_async16(sh_u32 + (unsigned)(WS_OFF(buf) + k * 136 + nq * 4) * 4u, src);
        }
        cp_commit();
    };

    float acc[4][4][4];
#pragma unroll
    for (int mt = 0; mt < 4; mt++)
#pragma unroll
        for (int nt = 0; nt < 4; nt++)
#pragma unroll
            for (int i = 0; i < 4; i++) acc[mt][nt][i] = 0.f;

    load_tiles(0, 0);

    for (int ks = 0; ks < INDIM / 16; ks++) {
        if (ks + 1 < INDIM / 16) { load_tiles(ks + 1, (ks + 1) & 1); cp_wait<1>(); }
        else cp_wait<0>();
        __syncthreads();

        const float* xs = sh + XS_OFF(ks & 1);
        const float* ws = sh + WS_OFF(ks & 1);

#pragma unroll
        for (int k8 = 0; k8 < 2; k8++) {
            const int kk = k8 * 8 + (lane & 3);
            unsigned bf0[4], bf1[4];
#pragma unroll
            for (int nt = 0; nt < 4; nt++) {
                const int n = wn * 32 + nt * 8 + (lane >> 2);
                bf0[nt] = __float_as_uint(to_tf32(ws[kk * 136 + n]));
                bf1[nt] = __float_as_uint(to_tf32(ws[(kk + 4) * 136 + n]));
            }
#pragma unroll
            for (int mt = 0; mt < 4; mt++) {
                const int row = wm * 64 + mt * 16 + (lane >> 2);
                const float f0 = xs[row * 20 + kk];
                const float f1 = xs[(row + 8) * 20 + kk];
                const float f2 = xs[row * 20 + kk + 4];
                const float f3 = xs[(row + 8) * 20 + kk + 4];
                const float h0 = to_tf32(f0), h1 = to_tf32(f1);
                const float h2 = to_tf32(f2), h3 = to_tf32(f3);
                const unsigned A0 = __float_as_uint(h0), A1 = __float_as_uint(h1);
                const unsigned A2 = __float_as_uint(h2), A3 = __float_as_uint(h3);
                const unsigned L0 = __float_as_uint(f0 - h0), L1 = __float_as_uint(f1 - h1);
                const unsigned L2 = __float_as_uint(f2 - h2), L3 = __float_as_uint(f3 - h3);
#pragma unroll
                for (int nt = 0; nt < 4; nt++) {
                    mma_tf32(acc[mt][nt], A0, A1, A2, A3, bf0[nt], bf1[nt]);
                    mma_tf32(acc[mt][nt], L0, L1, L2, L3, bf0[nt], bf1[nt]);
                }
            }
        }
        __syncthreads();
    }

    const int mrow = bm * 128 + wm * 64 + (lane >> 2);
    const int ncol = bn * 128 + wn * 32 + 2 * (lane & 3);
#pragma unroll
    for (int mt = 0; mt < 4; mt++)
#pragma unroll
        for (int nt = 0; nt < 4; nt++) {
            float* p0 = g_xz + (size_t)(mrow + mt * 16) * G4 + ncol + nt * 8;
            float* p1 = g_xz + (size_t)(mrow + mt * 16 + 8) * G4 + ncol + nt * 8;
            *(float2*)p0 = make_float2(acc[mt][nt][0], acc[mt][nt][1]);
            *(float2*)p1 = make_float2(acc[mt][nt][2], acc[mt][nt][3]);
        }
}

// ---------------- persistent recurrent kernel v16: fp16 mma ----------------
// smem: hs = h tile fp16 [32 b-rows][1032 halves] (2064 B/row, 66048 B),
//       zbuf at float offset 16512: [kq(4)][col(32)][34].
// Warp (mt = w>>2, kq = w&3): 16 k16-tiles (ktg = idx*4+kq), A-frags in regs
// (ah[16][4] uints). B-frags: bare LDS.32 from hs (conflict-free via pad).
// 64 mma/warp/step. Chunk = 16 b-rows (2 per step).
__global__ __launch_bounds__(NTHR, 1) void lstm_rec16(const float* __restrict__ bias,
                                                      const float* __restrict__ xz,
                                                      float* __restrict__ out) {
    extern __shared__ float sh[];
    float* zbuf = sh + 16512;
    const __half* hs = (const __half*)sh;
    const int tid  = threadIdx.x;
    const int lane = tid & 31;
    const int w    = tid >> 5;
    const int mt   = w >> 2;
    const int kq   = w & 3;
    const int cta  = blockIdx.x;
    const int u_g  = cta * 8 + w;

    unsigned sh_u32;
    {
        unsigned long long a = (unsigned long long)__cvta_generic_to_shared(sh);
        sh_u32 = (unsigned)a;
    }

    // A-frags (U fp16) -> registers, once
    unsigned ah[16][4];
    {
        const uint4* srcA = (const uint4*)g_Uph16;
#pragma unroll
        for (int idx = 0; idx < 16; idx++) {
            int ktg = idx * 4 + kq;
            uint4 v = srcA[((size_t)(cta * 2 + mt) * 64 + ktg) * 32 + lane];
            ah[idx][0] = v.x; ah[idx][1] = v.y; ah[idx][2] = v.z; ah[idx][3] = v.w;
        }
    }
    const float b_i = bias[u_g], b_f = bias[H + u_g],
                b_g = bias[2 * H + u_g], b_o = bias[3 * H + u_g];
    float cst = 0.f;

    // stage h(0): 64 KB -> hs, 2 commit groups (16 b-rows each)
    {
        const uint4* src = (const uint4*)g_h16[0];
#pragma unroll
        for (int k = 0; k < 16; k++) {
            int i = k * 256 + tid;                       // 16B unit index, 0..4095
            cp_async16(sh_u32 + (unsigned)(i >> 7) * 2064u + (unsigned)(i & 127) * 16u,
                       src + i);
            if (k == 7) cp_commit();
        }
        cp_commit();
    }

    for (int t = 0; t < TSTEPS; t++) {
        const size_t xb = ((size_t)lane * TSTEPS + t) * (size_t)G4 + u_g;
        const float x0 = xz[xb];
        const float x1 = xz[xb + H];
        const float x2 = xz[xb + 2 * H];
        const float x3 = xz[xb + 3 * H];

        float D[4][4];
#pragma unroll
        for (int nt = 0; nt < 4; nt++)
#pragma unroll
            for (int i = 0; i < 4; i++) D[nt][i] = 0.f;

#pragma unroll
        for (int c = 0; c < 2; c++) {
            if (c == 0) cp_wait<1>();
            else cp_wait<0>();
            __syncthreads();

#pragma unroll
            for (int j = 0; j < 16; j++) {
                const int ktg = j * 4 + kq;
                const int kof = ktg * 16 + 2 * (lane & 3);   // k offset of b0 pair
#pragma unroll
                for (int nl = 0; nl < 2; nl++) {
                    const int ntg = c * 2 + nl;
                    const int brow = ntg * 8 + (lane >> 2);
                    const unsigned b0 = *(const unsigned*)(hs + brow * 1032 + kof);
                    const unsigned b1 = *(const unsigned*)(hs + brow * 1032 + kof + 8);
                    mma_f16(D[ntg], ah[j][0], ah[j][1], ah[j][2], ah[j][3], b0, b1);
                }
            }
        }

        // write D -> zbuf [kq][col(32)][34]
        {
            const int r0 = mt * 16 + (lane >> 2);
            const int cb = 2 * (lane & 3);
#pragma unroll
            for (int nt = 0; nt < 4; nt++) {
                float* zp = zbuf + (kq * 32 + r0) * 34 + nt * 8 + cb;
                *(float2*)zp = make_float2(D[nt][0], D[nt][1]);
                *(float2*)(zp + 8 * 34) = make_float2(D[nt][2], D[nt][3]);
            }
        }
        __syncthreads();

        // pointwise (warp w = unit u_g, lane = batch)
        float zg4[4];
#pragma unroll
        for (int g = 0; g < 4; g++) {
            const int col = g * 8 + w;
            float s = zbuf[col * 34 + lane];
            s += zbuf[(32 + col) * 34 + lane];
            s += zbuf[(64 + col) * 34 + lane];
            s += zbuf[(96 + col) * 34 + lane];
            zg4[g] = s;
        }
        const float zi = zg4[0] + x0 + b_i;
        const float zf = zg4[1] + x1 + b_f;
        const float zc = zg4[2] + x2 + b_g;
        const float zo = zg4[3] + x3 + b_o;

        const float ig = 1.f / (1.f + __expf(-zi));
        const float fg = 1.f / (1.f + __expf(-zf));
        const float gv = tanhf(zc);
        const float og = 1.f / (1.f + __expf(-zo));

        cst = fg * cst + ig * gv;
        const float hval = og * tanhf(cst);

        out[((size_t)lane * TSTEPS + t) * H + u_g] = hval;
        g_h16[(t + 1) & 1][lane * H + u_g] = __float2half_rn(hval);   // [b][u]

        if (t == TSTEPS - 1) break;

        // ---- grid barrier: monotonic epoch counters, direct polling ----
        __threadfence();
        __syncthreads();
        const unsigned epoch = (unsigned)(t + 1);
        if (tid == 0) atomicAdd(&g_bar_cnt[(blockIdx.x & 7) * 32], 1u);
        if (tid < 32) {
            const unsigned need = epoch * (NCTA / 8);
            bool done;
            do {
                done = (lane >= 8) || (ld_cg_u32(&g_bar_cnt[lane * 32]) >= need);
            } while (!__all_sync(0xffffffffu, done));
            __threadfence();
        }
        __syncthreads();

        // stage h(t+1) into hs (single buffer: all compute on hs finished pre-barrier)
        {
            const uint4* src = (const uint4*)g_h16[(t + 1) & 1];
#pragma unroll
            for (int k = 0; k < 16; k++) {
                int i = k * 256 + tid;
                cp_async16(sh_u32 + (unsigned)(i >> 7) * 2064u + (unsigned)(i & 127) * 16u,
                           src + i);
                if (k == 7) cp_commit();
            }
            cp_commit();
        }
    }
}

// ---------------- launch ----------------
extern "C" void kernel_launch(void* const* d_in, const int* in_sizes, int n_in,
                              void* d_out, int out_size) {
    const float* x    = (const float*)d_in[0];  // [32,512,512]
    const float* W    = (const float*)d_in[1];  // [512,4096]
    const float* U    = (const float*)d_in[2];  // [1024,4096]
    const float* bias = (const float*)d_in[3];  // [4096]
    float* out = (float*)d_out;                 // [32,512,1024]

    static const int rec_smem  = (16512 + 4352) * (int)sizeof(float);  // 83456 B
    static const int gemm_smem = 9472 * (int)sizeof(float);            // 37888 B
    cudaFuncSetAttribute(lstm_rec16, cudaFuncAttributeMaxDynamicSharedMemorySize, rec_smem);
    cudaFuncSetAttribute(sgemm_tf32_kernel, cudaFuncAttributeMaxDynamicSharedMemorySize,
                         gemm_smem);

    float* xz_dev = nullptr;
    cudaGetSymbolAddress((void**)&xz_dev, g_xz);

    zero_h_kernel<<<(2 * BATCH * H / 2 + 255) / 256, 256>>>();
    pack_u16_kernel<<<2048, 256>>>(U);
    sgemm_tf32_kernel<<<dim3(G4 / 128, (BATCH * TSTEPS) / 128), 256, gemm_smem>>>(x, W);
    lstm_rec16<<<NCTA, NTHR, rec_smem>>>(bias, xz_dev, out);
}